// round 14
// baseline (speedup 1.0000x reference)
#include <cuda_runtime.h>
#include <cuda_bf16.h>
#include <math.h>
#include <stdint.h>

#define BB 8
#define QQ 2048
#define SS 2048
#define DD 512
#define EE 512

#define BKC 32
#define ROWB 80
#define NSTAGE 3
#define SMEM_SZ (NSTAGE * 2 * (128 + 256) * ROWB)   // 184320

typedef __nv_bfloat16 bf16;

// pre-split bf16 hi/lo operands (device-global scratch)
__device__ bf16 g_wth[(size_t)EE * DD],      g_wtl[(size_t)EE * DD];       // W^T
__device__ bf16 g_vth[(size_t)BB * EE * SS], g_vtl[(size_t)BB * EE * SS];  // values^T
__device__ bf16 g_tqh[(size_t)BB * QQ * EE], g_tql[(size_t)BB * QQ * EE];  // tq

__device__ __forceinline__ uint32_t s2u(const void* p) {
    uint32_t a;
    asm("{ .reg .u64 t; cvta.to.shared.u64 t, %1; cvt.u32.u64 %0, t; }" : "=r"(a) : "l"(p));
    return a;
}
__device__ __forceinline__ void split1(float v, bf16& h, bf16& l) {
    h = __float2bfloat16(v);
    l = __float2bfloat16(v - __bfloat162float(h));
}
__device__ __forceinline__ void cp16(uint32_t sa, const void* ga) {
    asm volatile("cp.async.cg.shared.global [%0], [%1], 16;" :: "r"(sa), "l"(ga) : "memory");
}
#define CP_COMMIT() asm volatile("cp.async.commit_group;" ::: "memory")
#define CP_WAIT(n)  asm volatile("cp.async.wait_group %0;" :: "n"(n) : "memory")
#define STS128U(addr, a, b, c, d) \
    asm volatile("st.shared.v4.b32 [%0], {%1, %2, %3, %4};" :: "r"(addr), "r"(a), "r"(b), "r"(c), "r"(d) : "memory")
#define LDSM4(r, addr) \
    asm volatile("ldmatrix.sync.aligned.m8n8.x4.shared.b16 {%0,%1,%2,%3}, [%4];" \
        : "=r"((r)[0]), "=r"((r)[1]), "=r"((r)[2]), "=r"((r)[3]) : "r"(addr))
#define MMA16816(d, a, b) \
    asm volatile("mma.sync.aligned.m16n8k16.row.col.f32.bf16.bf16.f32 " \
        "{%0,%1,%2,%3}, {%4,%5,%6,%7}, {%8,%9}, {%0,%1,%2,%3};" \
        : "+f"((d)[0]), "+f"((d)[1]), "+f"((d)[2]), "+f"((d)[3]) \
        : "r"((a)[0]), "r"((a)[1]), "r"((a)[2]), "r"((a)[3]), "r"((b)[0]), "r"((b)[1]))

__device__ __forceinline__ void cvt_sts16(const float4* r, uint32_t ha, uint32_t la) {
    uint32_t h[8], l[8];
    #pragma unroll
    for (int i = 0; i < 4; ++i) {
        bf16 hx, hy, hz, hw, lx, ly, lz, lw;
        split1(r[i].x, hx, lx); split1(r[i].y, hy, ly);
        split1(r[i].z, hz, lz); split1(r[i].w, hw, lw);
        h[2*i]   = (uint32_t)__bfloat16_as_ushort(hx) | ((uint32_t)__bfloat16_as_ushort(hy) << 16);
        h[2*i+1] = (uint32_t)__bfloat16_as_ushort(hz) | ((uint32_t)__bfloat16_as_ushort(hw) << 16);
        l[2*i]   = (uint32_t)__bfloat16_as_ushort(lx) | ((uint32_t)__bfloat16_as_ushort(ly) << 16);
        l[2*i+1] = (uint32_t)__bfloat16_as_ushort(lz) | ((uint32_t)__bfloat16_as_ushort(lw) << 16);
    }
    STS128U(ha, h[0], h[1], h[2], h[3]); STS128U(ha + 16, h[4], h[5], h[6], h[7]);
    STS128U(la, l[0], l[1], l[2], l[3]); STS128U(la + 16, l[4], l[5], l[6], l[7]);
}

// ---------------------------------------------------------------------------
// Transpose fp32 [R][C] -> hi/lo bf16 [C][R]. DSEL 0: W->wt, 1: values->vt.
// ---------------------------------------------------------------------------
template <int DSEL>
__global__ __launch_bounds__(256)
void trans_split(const float* __restrict__ src, int R, int C, long sS, long sD)
{
    __shared__ float t[32][33];
    bf16* dh = DSEL ? g_vth : g_wth;
    bf16* dl = DSEL ? g_vtl : g_wtl;
    src += (long)blockIdx.z * sS;
    dh  += (long)blockIdx.z * sD;
    dl  += (long)blockIdx.z * sD;
    const int r0 = blockIdx.y * 32, c0 = blockIdx.x * 32;
    const int tx = threadIdx.x & 31, ty = threadIdx.x >> 5;
    #pragma unroll
    for (int i = ty; i < 32; i += 8)
        t[i][tx] = src[(long)(r0 + i) * C + c0 + tx];
    __syncthreads();
    const int a = threadIdx.x & 15, iy = threadIdx.x >> 4;
    #pragma unroll
    for (int p = 0; p < 2; ++p) {
        int i = iy + p * 16;
        float v0 = t[2 * a][i], v1 = t[2 * a + 1][i];
        bf16 h0, h1, l0, l1;
        split1(v0, h0, l0); split1(v1, h1, l1);
        long o = (long)(c0 + i) * R + r0 + 2 * a;
        *(__nv_bfloat162*)(dh + o) = __nv_bfloat162(h0, h1);
        *(__nv_bfloat162*)(dl + o) = __nv_bfloat162(l0, l1);
    }
}

// ---------------------------------------------------------------------------
// NT GEMM, CTA CM x CN, warp tile 64x64, hi/lo compensated, 3-stage/1-sync.
// One operand side is fp32 "inline" (LDG -> split -> STS, register prefetch),
// the other is pre-split bf16 "async" (cp.async).
// ASYNC_A: 1 -> A is async, B inline.  0 -> B async, A inline.
// GSEL (async globals): 0=wt, 1=tq, 2=vt.
// EPI: 0=fp32, 1=fp32+mask, 2=split hi/lo to g_tqh/g_tql.
// ---------------------------------------------------------------------------
template <int ASYNC_A, int GSEL, int EPI, int CM, int CN>
__global__ __launch_bounds__(256, 1)
void mma_gemm(const float* __restrict__ Fg, const int* __restrict__ maskg,
              float* __restrict__ Cg, int K, int ldc, long sF, long sG, long sC)
{
    constexpr int OFF_AH = 0;
    constexpr int OFF_AL = CM * ROWB;
    constexpr int OFF_BH = 2 * CM * ROWB;
    constexpr int OFF_BL = OFF_BH + CN * ROWB;
    constexpr int STAGEB = 2 * (CM + CN) * ROWB;
    constexpr int WM = CM / 64;
    constexpr int AROWS = ASYNC_A ? CM : CN;    // async-side rows (always 128 here)
    constexpr int OFF_aH = ASYNC_A ? OFF_AH : OFF_BH;
    constexpr int OFF_aL = ASYNC_A ? OFF_AL : OFF_BL;
    constexpr int OFF_iH = ASYNC_A ? OFF_BH : OFF_AH;
    constexpr int OFF_iL = ASYNC_A ? OFF_BL : OFF_AL;
    extern __shared__ char smem[];
    const uint32_t sb = s2u(smem);
    const int tid = threadIdx.x, w = tid >> 5, lane = tid & 31;
    const int bz = blockIdx.z;
    const bf16* Gh = ((GSEL == 0) ? g_wth : (GSEL == 1) ? g_tqh : g_vth) + (size_t)bz * sG;
    const bf16* Gl = ((GSEL == 0) ? g_wtl : (GSEL == 1) ? g_tql : g_vtl) + (size_t)bz * sG;
    const float* F = Fg + (long)bz * sF;
    float* C = Cg + (long)bz * sC;
    const int bm = blockIdx.y * CM, bn = blockIdx.x * CN;
    const int base_a = ASYNC_A ? bm : bn;
    const int base_i = ASYNC_A ? bn : bm;
    const int m0 = (w % WM) * 64, n0 = (w / WM) * 64;

    float d[4][8][4] = {};
    float4 pre[2][4];     // inline-side register prefetch: 2 half-rows x 16 floats

    auto load_async = [&](uint32_t st, int kc) {
        uint32_t so = sb + st * STAGEB;
        #pragma unroll
        for (int j = 0; j < AROWS * 8 / 256; ++j) {
            int idx = tid + 256 * j;
            int half = idx / (AROWS * 4);
            int rem = idx - half * (AROWS * 4);
            int row = rem >> 2, q = rem & 3;
            const bf16* g = (half ? Gl : Gh) + (size_t)(base_a + row) * K + kc + q * 8;
            cp16(so + (half ? OFF_aL : OFF_aH) + row * ROWB + q * 16, g);
        }
    };
    auto ldg_inline = [&](int kc) {
        #pragma unroll
        for (int j = 0; j < 2; ++j) {
            int idx = tid + 256 * j;
            int row = idx >> 1, half = idx & 1;
            const float4* p = (const float4*)(F + (size_t)(base_i + row) * K + kc + half * 16);
            pre[j][0] = __ldg(p);     pre[j][1] = __ldg(p + 1);
            pre[j][2] = __ldg(p + 2); pre[j][3] = __ldg(p + 3);
        }
    };
    auto sts_inline = [&](uint32_t st) {
        uint32_t so = sb + st * STAGEB;
        #pragma unroll
        for (int j = 0; j < 2; ++j) {
            int idx = tid + 256 * j;
            int row = idx >> 1, half = idx & 1;
            cvt_sts16(pre[j], so + OFF_iH + row * ROWB + half * 32,
                              so + OFF_iL + row * ROWB + half * 32);
        }
    };

    // prologue: stage 0 fully staged; stage 1 async in flight + fp32 in regs
    ldg_inline(0);
    sts_inline(0);
    load_async(0, 0);  CP_COMMIT();
    ldg_inline(BKC);
    load_async(1, BKC); CP_COMMIT();

    const int NC = K / BKC;
    for (int c = 0; c < NC; ++c) {
        CP_WAIT(1);            // THIS thread's stage-c async group complete
        __syncthreads();       // ...published to all warps; stage c-1 reads done
        if (c + 1 < NC) sts_inline((c + 1) % NSTAGE);       // from regs (chunk c+1)
        if (c + 2 < NC) load_async((c + 2) % NSTAGE, (c + 2) * BKC);
        CP_COMMIT();           // always commit to keep group counts aligned
        if (c + 2 < NC) ldg_inline((c + 2) * BKC);
        const uint32_t stage = sb + (uint32_t)((c % NSTAGE) * STAGEB);
        #pragma unroll
        for (int ks = 0; ks < 2; ++ks) {
            uint32_t ah[4][4], al[4][4], bh[8][2], bl[8][2];
            const uint32_t akoff = ks * 32 + (lane >> 4) * 16;
            #pragma unroll
            for (int mt = 0; mt < 4; ++mt) {
                uint32_t ro = (uint32_t)((m0 + mt * 16 + (lane & 15)) * ROWB);
                LDSM4(ah[mt], stage + OFF_AH + ro + akoff);
                LDSM4(al[mt], stage + OFF_AL + ro + akoff);
            }
            const uint32_t bkoff = ks * 32 + ((lane >> 3) & 1) * 16;
            #pragma unroll
            for (int np = 0; np < 4; ++np) {
                uint32_t ro = (uint32_t)((n0 + np * 16 + ((lane >> 4) << 3) + (lane & 7)) * ROWB);
                uint32_t r4[4];
                LDSM4(r4, stage + OFF_BH + ro + bkoff);
                bh[np*2][0] = r4[0]; bh[np*2][1] = r4[1];
                bh[np*2+1][0] = r4[2]; bh[np*2+1][1] = r4[3];
                LDSM4(r4, stage + OFF_BL + ro + bkoff);
                bl[np*2][0] = r4[0]; bl[np*2][1] = r4[1];
                bl[np*2+1][0] = r4[2]; bl[np*2+1][1] = r4[3];
            }
            #pragma unroll
            for (int mt = 0; mt < 4; ++mt)
                #pragma unroll
                for (int nt = 0; nt < 8; ++nt) {
                    MMA16816(d[mt][nt], ah[mt], bh[nt]);
                    MMA16816(d[mt][nt], ah[mt], bl[nt]);
                    MMA16816(d[mt][nt], al[mt], bh[nt]);
                }
        }
    }

    const int* mrow = (EPI == 1) ? (maskg + (long)bz * ldc) : (const int*)0;
    #pragma unroll
    for (int mt = 0; mt < 4; ++mt) {
        #pragma unroll
        for (int nt = 0; nt < 8; ++nt) {
            int r0 = bm + m0 + mt * 16 + (lane >> 2);
            int col = bn + n0 + nt * 8 + (lane & 3) * 2;
            float v0 = d[mt][nt][0], v1 = d[mt][nt][1];
            float v2 = d[mt][nt][2], v3 = d[mt][nt][3];
            if (EPI == 1) {
                int k0 = __ldg(mrow + col), k1 = __ldg(mrow + col + 1);
                if (!k0) { v0 = -INFINITY; v2 = -INFINITY; }
                if (!k1) { v1 = -INFINITY; v3 = -INFINITY; }
            }
            if (EPI == 2) {
                size_t o0 = (size_t)r0 * ldc + col, o1 = (size_t)(r0 + 8) * ldc + col;
                bf16 h0, h1, h2, h3, l0, l1, l2, l3;
                split1(v0, h0, l0); split1(v1, h1, l1);
                split1(v2, h2, l2); split1(v3, h3, l3);
                *(__nv_bfloat162*)(g_tqh + o0) = __nv_bfloat162(h0, h1);
                *(__nv_bfloat162*)(g_tql + o0) = __nv_bfloat162(l0, l1);
                *(__nv_bfloat162*)(g_tqh + o1) = __nv_bfloat162(h2, h3);
                *(__nv_bfloat162*)(g_tql + o1) = __nv_bfloat162(l2, l3);
            } else {
                *(float2*)(C + (long)r0 * ldc + col)       = make_float2(v0, v1);
                *(float2*)(C + (long)(r0 + 8) * ldc + col) = make_float2(v2, v3);
            }
        }
    }
}

// ---------------------------------------------------------------------------
// In-place row softmax over S=2048 columns (fp32 only).
// ---------------------------------------------------------------------------
__global__ __launch_bounds__(256)
void softmax_rows(float* __restrict__ attn)
{
    __shared__ float sm[32];
    const long row = blockIdx.x;
    float4* p = (float4*)(attn + row * (long)SS);
    const int t = threadIdx.x, lane = t & 31, wid = t >> 5;
    float4 v0 = p[t], v1 = p[t + 256];
    float m = fmaxf(fmaxf(fmaxf(v0.x, v0.y), fmaxf(v0.z, v0.w)),
                    fmaxf(fmaxf(v1.x, v1.y), fmaxf(v1.z, v1.w)));
    #pragma unroll
    for (int o = 16; o; o >>= 1) m = fmaxf(m, __shfl_xor_sync(0xffffffffu, m, o));
    if (lane == 0) sm[wid] = m;
    __syncthreads();
    if (t == 0) {
        float x = sm[0];
        #pragma unroll
        for (int i = 1; i < 8; ++i) x = fmaxf(x, sm[i]);
        sm[8] = x;
    }
    __syncthreads();
    const float rm = sm[8];
    v0.x = expf(v0.x - rm); v0.y = expf(v0.y - rm);
    v0.z = expf(v0.z - rm); v0.w = expf(v0.w - rm);
    v1.x = expf(v1.x - rm); v1.y = expf(v1.y - rm);
    v1.z = expf(v1.z - rm); v1.w = expf(v1.w - rm);
    float s = (v0.x + v0.y + v0.z + v0.w) + (v1.x + v1.y + v1.z + v1.w);
    #pragma unroll
    for (int o = 16; o; o >>= 1) s += __shfl_xor_sync(0xffffffffu, s, o);
    if (lane == 0) sm[16 + wid] = s;
    __syncthreads();
    if (t == 0) {
        float x = 0.0f;
        #pragma unroll
        for (int i = 0; i < 8; ++i) x += sm[16 + i];
        sm[24] = x;
    }
    __syncthreads();
    const float inv = 1.0f / sm[24];
    v0.x *= inv; v0.y *= inv; v0.z *= inv; v0.w *= inv;
    v1.x *= inv; v1.y *= inv; v1.z *= inv; v1.w *= inv;
    p[t] = v0; p[t + 256] = v1;
}

extern "C" void kernel_launch(void* const* d_in, const int* in_sizes, int n_in,
                              void* d_out, int out_size)
{
    const float* query  = (const float*)d_in[0];
    const float* values = (const float*)d_in[1];
    const int*   mask   = (const int*)d_in[2];
    const float* W      = (const float*)d_in[3];

    float* context = (float*)d_out;
    float* attn    = (float*)d_out + (size_t)BB * QQ * EE;

    cudaFuncSetAttribute(mma_gemm<0,0,2,256,128>, cudaFuncAttributeMaxDynamicSharedMemorySize, SMEM_SZ);
    cudaFuncSetAttribute(mma_gemm<1,1,1,128,256>, cudaFuncAttributeMaxDynamicSharedMemorySize, SMEM_SZ);
    cudaFuncSetAttribute(mma_gemm<0,2,0,256,128>, cudaFuncAttributeMaxDynamicSharedMemorySize, SMEM_SZ);

    // prep: transposed hi/lo operands only
    trans_split<0><<<dim3(EE/32, DD/32, 1), 256>>>(W, DD, EE, 0L, 0L);
    trans_split<1><<<dim3(EE/32, SS/32, BB), 256>>>(values, SS, EE,
        (long)SS*EE, (long)EE*SS);

    // G1: tq = query @ W^T'   A inline (query fp32), B async (wt) -> hi/lo tq
    mma_gemm<0,0,2,256,128><<<dim3(EE/128, (BB*QQ)/256, 1), 256, SMEM_SZ>>>(
        query, (const int*)0, (float*)0, DD, EE, 0L, 0L, 0L);

    // G2: scores = tq @ values^T + mask   A async (tq), B inline (values fp32)
    mma_gemm<1,1,1,128,256><<<dim3(SS/256, QQ/128, BB), 256, SMEM_SZ>>>(
        values, mask, attn, EE, SS, (long)SS*EE, (long)QQ*EE, (long)QQ*SS);

    // softmax in place (fp32 only)
    softmax_rows<<<BB*QQ, 256>>>(attn);

    // G3: context = attn @ values   A inline (attn fp32), B async (vt)
    mma_gemm<0,2,0,256,128><<<dim3(EE/128, QQ/256, BB), 256, SMEM_SZ>>>(
        attn, (const int*)0, context, SS, EE, (long)QQ*SS, (long)EE*SS, (long)QQ*EE);
}

// round 15
// speedup vs baseline: 1.1556x; 1.1556x over previous
#include <cuda_runtime.h>
#include <cuda_bf16.h>
#include <math.h>
#include <stdint.h>

#define BB 8
#define QQ 2048
#define SS 2048
#define DD 512
#define EE 512

#define BKC 32
#define ROWB 80
#define NSTAGE 3
#define SMEM_SZ (NSTAGE * 2 * (128 + 256) * ROWB)   // 184320

typedef __nv_bfloat16 bf16;

// hi/lo split operands (device-global scratch)
__device__ bf16 g_qh[(size_t)BB * QQ * DD], g_ql[(size_t)BB * QQ * DD];
__device__ bf16 g_wth[(size_t)EE * DD],     g_wtl[(size_t)EE * DD];
__device__ bf16 g_vh[(size_t)BB * SS * EE], g_vl[(size_t)BB * SS * EE];
__device__ bf16 g_vth[(size_t)BB * EE * SS], g_vtl[(size_t)BB * EE * SS];
__device__ bf16 g_tqh[(size_t)BB * QQ * EE], g_tql[(size_t)BB * QQ * EE];
__device__ bf16 g_ah[(size_t)BB * QQ * SS], g_al[(size_t)BB * QQ * SS];

__device__ __forceinline__ uint32_t s2u(const void* p) {
    uint32_t a;
    asm("{ .reg .u64 t; cvta.to.shared.u64 t, %1; cvt.u32.u64 %0, t; }" : "=r"(a) : "l"(p));
    return a;
}
__device__ __forceinline__ void split1(float v, bf16& h, bf16& l) {
    h = __float2bfloat16(v);
    l = __float2bfloat16(v - __bfloat162float(h));
}
__device__ __forceinline__ void cp16(uint32_t sa, const void* ga) {
    asm volatile("cp.async.cg.shared.global [%0], [%1], 16;" :: "r"(sa), "l"(ga) : "memory");
}
#define CP_COMMIT() asm volatile("cp.async.commit_group;" ::: "memory")
#define CP_WAIT(n)  asm volatile("cp.async.wait_group %0;" :: "n"(n) : "memory")
#define LDSM4(r, addr) \
    asm volatile("ldmatrix.sync.aligned.m8n8.x4.shared.b16 {%0,%1,%2,%3}, [%4];" \
        : "=r"((r)[0]), "=r"((r)[1]), "=r"((r)[2]), "=r"((r)[3]) : "r"(addr))
#define MMA16816(d, a, b) \
    asm volatile("mma.sync.aligned.m16n8k16.row.col.f32.bf16.bf16.f32 " \
        "{%0,%1,%2,%3}, {%4,%5,%6,%7}, {%8,%9}, {%0,%1,%2,%3};" \
        : "+f"((d)[0]), "+f"((d)[1]), "+f"((d)[2]), "+f"((d)[3]) \
        : "r"((a)[0]), "r"((a)[1]), "r"((a)[2]), "r"((a)[3]), "r"((b)[0]), "r"((b)[1]))

// ---------------------------------------------------------------------------
// query fp32 -> hi/lo bf16 (same layout).
// ---------------------------------------------------------------------------
__global__ __launch_bounds__(256)
void conv_query(const float* __restrict__ src)
{
    size_t i = ((size_t)blockIdx.x * 256 + threadIdx.x) * 4;
    float4 v = __ldg((const float4*)(src + i));
    bf16 h0, h1, h2, h3, l0, l1, l2, l3;
    split1(v.x, h0, l0); split1(v.y, h1, l1);
    split1(v.z, h2, l2); split1(v.w, h3, l3);
    __nv_bfloat162* ph = (__nv_bfloat162*)(g_qh + i);
    __nv_bfloat162* pl = (__nv_bfloat162*)(g_ql + i);
    ph[0] = __nv_bfloat162(h0, h1); ph[1] = __nv_bfloat162(h2, h3);
    pl[0] = __nv_bfloat162(l0, l1); pl[1] = __nv_bfloat162(l2, l3);
}

// ---------------------------------------------------------------------------
// W fp32 [D][E] -> transposed hi/lo bf16 [E][D].
// ---------------------------------------------------------------------------
__global__ __launch_bounds__(256)
void trans_w(const float* __restrict__ src)
{
    __shared__ float t[32][33];
    const int r0 = blockIdx.y * 32, c0 = blockIdx.x * 32;
    const int tx = threadIdx.x & 31, ty = threadIdx.x >> 5;
    #pragma unroll
    for (int i = ty; i < 32; i += 8)
        t[i][tx] = src[(long)(r0 + i) * EE + c0 + tx];
    __syncthreads();
    const int a = threadIdx.x & 15, iy = threadIdx.x >> 4;
    #pragma unroll
    for (int p = 0; p < 2; ++p) {
        int i = iy + p * 16;
        float v0 = t[2 * a][i], v1 = t[2 * a + 1][i];
        bf16 h0, h1, l0, l1;
        split1(v0, h0, l0); split1(v1, h1, l1);
        long o = (long)(c0 + i) * DD + r0 + 2 * a;
        *(__nv_bfloat162*)(g_wth + o) = __nv_bfloat162(h0, h1);
        *(__nv_bfloat162*)(g_wtl + o) = __nv_bfloat162(l0, l1);
    }
}

// ---------------------------------------------------------------------------
// values fp32 [B][S][E]: one read -> g_vh/g_vl (same layout) AND
// g_vth/g_vtl (transposed [B][E][S]).
// ---------------------------------------------------------------------------
__global__ __launch_bounds__(256)
void prep_values(const float* __restrict__ src)
{
    __shared__ float t[32][33];
    const long zb = (long)blockIdx.z;
    src   += zb * SS * EE;
    bf16* vh  = g_vh  + zb * SS * EE;
    bf16* vl  = g_vl  + zb * SS * EE;
    bf16* vth = g_vth + zb * EE * SS;
    bf16* vtl = g_vtl + zb * EE * SS;
    const int r0 = blockIdx.y * 32, c0 = blockIdx.x * 32;  // r = S, c = E
    const int tx = threadIdx.x & 31, ty = threadIdx.x >> 5;
    #pragma unroll
    for (int i = ty; i < 32; i += 8)
        t[i][tx] = src[(long)(r0 + i) * EE + c0 + tx];
    __syncthreads();
    const int a = threadIdx.x & 15, iy = threadIdx.x >> 4;
    #pragma unroll
    for (int p = 0; p < 2; ++p) {
        int i = iy + p * 16;
        // row-major out: row r0+i, cols c0+2a..2a+1
        {
            float v0 = t[i][2 * a], v1 = t[i][2 * a + 1];
            bf16 h0, h1, l0, l1;
            split1(v0, h0, l0); split1(v1, h1, l1);
            long o = (long)(r0 + i) * EE + c0 + 2 * a;
            *(__nv_bfloat162*)(vh + o) = __nv_bfloat162(h0, h1);
            *(__nv_bfloat162*)(vl + o) = __nv_bfloat162(l0, l1);
        }
        // transposed out: row c0+i, cols r0+2a..2a+1
        {
            float v0 = t[2 * a][i], v1 = t[2 * a + 1][i];
            bf16 h0, h1, l0, l1;
            split1(v0, h0, l0); split1(v1, h1, l1);
            long o = (long)(c0 + i) * SS + r0 + 2 * a;
            *(__nv_bfloat162*)(vth + o) = __nv_bfloat162(h0, h1);
            *(__nv_bfloat162*)(vtl + o) = __nv_bfloat162(l0, l1);
        }
    }
}

// ---------------------------------------------------------------------------
// NT GEMM on pre-split bf16 hi/lo operands, 3-stage cp.async, 1 sync/chunk.
// ASEL: 0=query, 1=tq, 2=attn.  BSEL: 0=wt, 1=values, 2=vt.
// EPI: 0=fp32, 1=fp32+mask, 2=split hi/lo to g_tqh/g_tql.
// z0: batch offset (stream-split).
// ---------------------------------------------------------------------------
template <int ASEL, int BSEL, int EPI, int CM, int CN>
__global__ __launch_bounds__(256, 1)
void mma_gemm(const int* __restrict__ maskg, float* __restrict__ Cg,
              int K, int ldc, long sA, long sB, long sC, int z0)
{
    constexpr int OFF_AH = 0;
    constexpr int OFF_AL = CM * ROWB;
    constexpr int OFF_BH = 2 * CM * ROWB;
    constexpr int OFF_BL = OFF_BH + CN * ROWB;
    constexpr int STAGEB = 2 * (CM + CN) * ROWB;
    constexpr int WM = CM / 64;
    extern __shared__ char smem[];
    const uint32_t sb = s2u(smem);
    const int tid = threadIdx.x, w = tid >> 5, lane = tid & 31;
    const int bz = blockIdx.z + z0;
    const bf16* Ah = ((ASEL == 0) ? g_qh : (ASEL == 1) ? g_tqh : g_ah) + (size_t)bz * sA;
    const bf16* Al = ((ASEL == 0) ? g_ql : (ASEL == 1) ? g_tql : g_al) + (size_t)bz * sA;
    const bf16* Bh = ((BSEL == 0) ? g_wth : (BSEL == 1) ? g_vh : g_vth) + (size_t)bz * sB;
    const bf16* Bl = ((BSEL == 0) ? g_wtl : (BSEL == 1) ? g_vl : g_vtl) + (size_t)bz * sB;
    float* C = Cg + (long)bz * sC;
    const int bm = blockIdx.y * CM, bn = blockIdx.x * CN;
    const int m0 = (w % WM) * 64, n0 = (w / WM) * 64;

    float d[4][8][4] = {};

    auto load_stage = [&](uint32_t st, int kc) {
        uint32_t so = sb + st * STAGEB;
        #pragma unroll
        for (int j = 0; j < CM * 8 / 256; ++j) {
            int idx = tid + 256 * j;
            int half = idx / (CM * 4);
            int rem = idx - half * (CM * 4);
            int row = rem >> 2, q = rem & 3;
            const bf16* g = (half ? Al : Ah) + (size_t)(bm + row) * K + kc + q * 8;
            cp16(so + (half ? OFF_AL : OFF_AH) + row * ROWB + q * 16, g);
        }
        #pragma unroll
        for (int j = 0; j < CN * 8 / 256; ++j) {
            int idx = tid + 256 * j;
            int half = idx / (CN * 4);
            int rem = idx - half * (CN * 4);
            int row = rem >> 2, q = rem & 3;
            const bf16* g = (half ? Bl : Bh) + (size_t)(bn + row) * K + kc + q * 8;
            cp16(so + (half ? OFF_BL : OFF_BH) + row * ROWB + q * 16, g);
        }
    };

    load_stage(0, 0);
    CP_COMMIT();
    load_stage(1, BKC);
    CP_COMMIT();

    const int NC = K / BKC;
    for (int c = 0; c < NC; ++c) {
        CP_WAIT(1);
        __syncthreads();
        if (c + 2 < NC)
            load_stage((c + 2) % NSTAGE, (c + 2) * BKC);
        CP_COMMIT();
        const uint32_t stage = sb + (uint32_t)((c % NSTAGE) * STAGEB);
        #pragma unroll
        for (int ks = 0; ks < 2; ++ks) {
            uint32_t ah[4][4], al[4][4], bh[8][2], bl[8][2];
            const uint32_t akoff = ks * 32 + (lane >> 4) * 16;
            #pragma unroll
            for (int mt = 0; mt < 4; ++mt) {
                uint32_t ro = (uint32_t)((m0 + mt * 16 + (lane & 15)) * ROWB);
                LDSM4(ah[mt], stage + OFF_AH + ro + akoff);
                LDSM4(al[mt], stage + OFF_AL + ro + akoff);
            }
            const uint32_t bkoff = ks * 32 + ((lane >> 3) & 1) * 16;
            #pragma unroll
            for (int np = 0; np < 4; ++np) {
                uint32_t ro = (uint32_t)((n0 + np * 16 + ((lane >> 4) << 3) + (lane & 7)) * ROWB);
                uint32_t r4[4];
                LDSM4(r4, stage + OFF_BH + ro + bkoff);
                bh[np*2][0] = r4[0]; bh[np*2][1] = r4[1];
                bh[np*2+1][0] = r4[2]; bh[np*2+1][1] = r4[3];
                LDSM4(r4, stage + OFF_BL + ro + bkoff);
                bl[np*2][0] = r4[0]; bl[np*2][1] = r4[1];
                bl[np*2+1][0] = r4[2]; bl[np*2+1][1] = r4[3];
            }
            #pragma unroll
            for (int mt = 0; mt < 4; ++mt)
                #pragma unroll
                for (int nt = 0; nt < 8; ++nt) {
                    MMA16816(d[mt][nt], ah[mt], bh[nt]);
                    MMA16816(d[mt][nt], ah[mt], bl[nt]);
                    MMA16816(d[mt][nt], al[mt], bh[nt]);
                }
        }
    }

    const int* mrow = (EPI == 1) ? (maskg + (long)bz * ldc) : (const int*)0;
    #pragma unroll
    for (int mt = 0; mt < 4; ++mt) {
        #pragma unroll
        for (int nt = 0; nt < 8; ++nt) {
            int r0 = bm + m0 + mt * 16 + (lane >> 2);
            int col = bn + n0 + nt * 8 + (lane & 3) * 2;
            float v0 = d[mt][nt][0], v1 = d[mt][nt][1];
            float v2 = d[mt][nt][2], v3 = d[mt][nt][3];
            if (EPI == 1) {
                int k0 = __ldg(mrow + col), k1 = __ldg(mrow + col + 1);
                if (!k0) { v0 = -INFINITY; v2 = -INFINITY; }
                if (!k1) { v1 = -INFINITY; v3 = -INFINITY; }
            }
            if (EPI == 2) {
                size_t o0 = (size_t)r0 * ldc + col, o1 = (size_t)(r0 + 8) * ldc + col;
                bf16 h0, h1, h2, h3, l0, l1, l2, l3;
                split1(v0, h0, l0); split1(v1, h1, l1);
                split1(v2, h2, l2); split1(v3, h3, l3);
                *(__nv_bfloat162*)(g_tqh + o0) = __nv_bfloat162(h0, h1);
                *(__nv_bfloat162*)(g_tql + o0) = __nv_bfloat162(l0, l1);
                *(__nv_bfloat162*)(g_tqh + o1) = __nv_bfloat162(h2, h3);
                *(__nv_bfloat162*)(g_tql + o1) = __nv_bfloat162(l2, l3);
            } else {
                *(float2*)(C + (long)r0 * ldc + col)       = make_float2(v0, v1);
                *(float2*)(C + (long)(r0 + 8) * ldc + col) = make_float2(v2, v3);
            }
        }
    }
}

// ---------------------------------------------------------------------------
// In-place row softmax; emits hi/lo bf16 copy for G3. row0: stream-split offset.
// ---------------------------------------------------------------------------
__global__ __launch_bounds__(256)
void softmax_rows(float* __restrict__ attn, long row0)
{
    __shared__ float sm[32];
    const long row = row0 + blockIdx.x;
    float4* p = (float4*)(attn + row * (long)SS);
    const int t = threadIdx.x, lane = t & 31, wid = t >> 5;
    float4 v0 = p[t], v1 = p[t + 256];
    float m = fmaxf(fmaxf(fmaxf(v0.x, v0.y), fmaxf(v0.z, v0.w)),
                    fmaxf(fmaxf(v1.x, v1.y), fmaxf(v1.z, v1.w)));
    #pragma unroll
    for (int o = 16; o; o >>= 1) m = fmaxf(m, __shfl_xor_sync(0xffffffffu, m, o));
    if (lane == 0) sm[wid] = m;
    __syncthreads();
    if (t == 0) {
        float x = sm[0];
        #pragma unroll
        for (int i = 1; i < 8; ++i) x = fmaxf(x, sm[i]);
        sm[8] = x;
    }
    __syncthreads();
    const float rm = sm[8];
    v0.x = expf(v0.x - rm); v0.y = expf(v0.y - rm);
    v0.z = expf(v0.z - rm); v0.w = expf(v0.w - rm);
    v1.x = expf(v1.x - rm); v1.y = expf(v1.y - rm);
    v1.z = expf(v1.z - rm); v1.w = expf(v1.w - rm);
    float s = (v0.x + v0.y + v0.z + v0.w) + (v1.x + v1.y + v1.z + v1.w);
    #pragma unroll
    for (int o = 16; o; o >>= 1) s += __shfl_xor_sync(0xffffffffu, s, o);
    if (lane == 0) sm[16 + wid] = s;
    __syncthreads();
    if (t == 0) {
        float x = 0.0f;
        #pragma unroll
        for (int i = 0; i < 8; ++i) x += sm[16 + i];
        sm[24] = x;
    }
    __syncthreads();
    const float inv = 1.0f / sm[24];
    v0.x *= inv; v0.y *= inv; v0.z *= inv; v0.w *= inv;
    v1.x *= inv; v1.y *= inv; v1.z *= inv; v1.w *= inv;
    p[t] = v0; p[t + 256] = v1;

    const size_t base = (size_t)row * SS;
    float vv[8] = {v0.x, v0.y, v0.z, v0.w, v1.x, v1.y, v1.z, v1.w};
    size_t off[2] = {base + (size_t)t * 4, base + (size_t)(t + 256) * 4};
    #pragma unroll
    for (int g = 0; g < 2; ++g) {
        bf16 h0, h1, h2, h3, l0, l1, l2, l3;
        split1(vv[g*4+0], h0, l0); split1(vv[g*4+1], h1, l1);
        split1(vv[g*4+2], h2, l2); split1(vv[g*4+3], h3, l3);
        __nv_bfloat162* ph = (__nv_bfloat162*)(g_ah + off[g]);
        __nv_bfloat162* pl = (__nv_bfloat162*)(g_al + off[g]);
        ph[0] = __nv_bfloat162(h0, h1); ph[1] = __nv_bfloat162(h2, h3);
        pl[0] = __nv_bfloat162(l0, l1); pl[1] = __nv_bfloat162(l2, l3);
    }
}

extern "C" void kernel_launch(void* const* d_in, const int* in_sizes, int n_in,
                              void* d_out, int out_size)
{
    const float* query  = (const float*)d_in[0];
    const float* values = (const float*)d_in[1];
    const int*   mask   = (const int*)d_in[2];
    const float* W      = (const float*)d_in[3];

    float* context = (float*)d_out;
    float* attn    = (float*)d_out + (size_t)BB * QQ * EE;

    static cudaStream_t s2 = nullptr;
    static cudaEvent_t ev0 = nullptr, evG1 = nullptr, evPV = nullptr, evEnd = nullptr;
    if (!s2) {
        cudaStreamCreateWithFlags(&s2, cudaStreamNonBlocking);
        cudaEventCreateWithFlags(&ev0,  cudaEventDisableTiming);
        cudaEventCreateWithFlags(&evG1, cudaEventDisableTiming);
        cudaEventCreateWithFlags(&evPV, cudaEventDisableTiming);
        cudaEventCreateWithFlags(&evEnd, cudaEventDisableTiming);
    }

    cudaFuncSetAttribute(mma_gemm<0,0,2,256,128>, cudaFuncAttributeMaxDynamicSharedMemorySize, SMEM_SZ);
    cudaFuncSetAttribute(mma_gemm<1,1,1,128,256>, cudaFuncAttributeMaxDynamicSharedMemorySize, SMEM_SZ);
    cudaFuncSetAttribute(mma_gemm<2,2,0,256,128>, cudaFuncAttributeMaxDynamicSharedMemorySize, SMEM_SZ);

    // fork: aux stream joins the capture graph
    cudaEventRecord(ev0, 0);
    cudaStreamWaitEvent(s2, ev0, 0);

    // stream 0: query split, W^T split, G1
    conv_query<<<(BB*QQ*DD)/1024, 256>>>(query);
    trans_w<<<dim3(EE/32, DD/32, 1), 256>>>(W);
    mma_gemm<0,0,2,256,128><<<dim3(EE/128, (BB*QQ)/256, 1), 256, SMEM_SZ>>>(
        (const int*)0, (float*)0, DD, EE, 0L, 0L, 0L, 0);
    cudaEventRecord(evG1, 0);

    // stream s2: values -> vh/vl + vth/vtl (single read)
    prep_values<<<dim3(EE/32, SS/32, BB), 256, 0, s2>>>(values);
    cudaEventRecord(evPV, s2);

    // cross deps: each chain needs both G1 (tq) and prep_values
    cudaStreamWaitEvent(0, evPV, 0);
    cudaStreamWaitEvent(s2, evG1, 0);

    // chain A (batches 0-3) on stream 0; chain B (4-7) on s2
    mma_gemm<1,1,1,128,256><<<dim3(SS/256, QQ/128, 4), 256, SMEM_SZ>>>(
        mask, attn, EE, SS, (long)QQ*EE, (long)SS*EE, (long)QQ*SS, 0);
    mma_gemm<1,1,1,128,256><<<dim3(SS/256, QQ/128, 4), 256, SMEM_SZ, s2>>>(
        mask, attn, EE, SS, (long)QQ*EE, (long)SS*EE, (long)QQ*SS, 4);

    softmax_rows<<<4*QQ, 256>>>(attn, 0L);
    softmax_rows<<<4*QQ, 256, 0, s2>>>(attn, (long)4*QQ);

    mma_gemm<2,2,0,256,128><<<dim3(EE/128, QQ/256, 4), 256, SMEM_SZ>>>(
        (const int*)0, context, SS, EE, (long)QQ*SS, (long)EE*SS, (long)QQ*EE, 0);
    mma_gemm<2,2,0,256,128><<<dim3(EE/128, QQ/256, 4), 256, SMEM_SZ, s2>>>(
        (const int*)0, context, SS, EE, (long)QQ*SS, (long)EE*SS, (long)QQ*EE, 4);

    // join: stream 0 waits for chain B
    cudaEventRecord(evEnd, s2);
    cudaStreamWaitEvent(0, evEnd, 0);
}

// round 16
// speedup vs baseline: 1.1793x; 1.0205x over previous
#include <cuda_runtime.h>
#include <cuda_bf16.h>
#include <math.h>
#include <stdint.h>

#define BB 8
#define QQ 2048
#define SS 2048
#define DD 512
#define EE 512

#define BKC 32
#define ROWB 80
#define NSTAGE 3
#define SMEM_SZ (NSTAGE * 2 * (128 + 256) * ROWB)   // 184320

typedef __nv_bfloat16 bf16;

// hi/lo split operands (device-global scratch)
__device__ bf16 g_qh[(size_t)BB * QQ * DD], g_ql[(size_t)BB * QQ * DD];
__device__ bf16 g_wth[(size_t)EE * DD],     g_wtl[(size_t)EE * DD];
__device__ bf16 g_vh[(size_t)BB * SS * EE], g_vl[(size_t)BB * SS * EE];
__device__ bf16 g_vth[(size_t)BB * EE * SS], g_vtl[(size_t)BB * EE * SS];
__device__ bf16 g_tqh[(size_t)BB * QQ * EE], g_tql[(size_t)BB * QQ * EE];
__device__ bf16 g_ah[(size_t)BB * QQ * SS], g_al[(size_t)BB * QQ * SS];

__device__ __forceinline__ uint32_t s2u(const void* p) {
    uint32_t a;
    asm("{ .reg .u64 t; cvta.to.shared.u64 t, %1; cvt.u32.u64 %0, t; }" : "=r"(a) : "l"(p));
    return a;
}
__device__ __forceinline__ void split1(float v, bf16& h, bf16& l) {
    h = __float2bfloat16(v);
    l = __float2bfloat16(v - __bfloat162float(h));
}
__device__ __forceinline__ void cp16(uint32_t sa, const void* ga) {
    asm volatile("cp.async.cg.shared.global [%0], [%1], 16;" :: "r"(sa), "l"(ga) : "memory");
}
#define CP_COMMIT() asm volatile("cp.async.commit_group;" ::: "memory")
#define CP_WAIT(n)  asm volatile("cp.async.wait_group %0;" :: "n"(n) : "memory")
#define LDSM4(r, addr) \
    asm volatile("ldmatrix.sync.aligned.m8n8.x4.shared.b16 {%0,%1,%2,%3}, [%4];" \
        : "=r"((r)[0]), "=r"((r)[1]), "=r"((r)[2]), "=r"((r)[3]) : "r"(addr))
#define MMA16816(d, a, b) \
    asm volatile("mma.sync.aligned.m16n8k16.row.col.f32.bf16.bf16.f32 " \
        "{%0,%1,%2,%3}, {%4,%5,%6,%7}, {%8,%9}, {%0,%1,%2,%3};" \
        : "+f"((d)[0]), "+f"((d)[1]), "+f"((d)[2]), "+f"((d)[3]) \
        : "r"((a)[0]), "r"((a)[1]), "r"((a)[2]), "r"((a)[3]), "r"((b)[0]), "r"((b)[1]))

// ---------------------------------------------------------------------------
// query fp32 -> hi/lo bf16 (same layout). x0: block offset for stream split.
// ---------------------------------------------------------------------------
__global__ __launch_bounds__(256)
void conv_query(const float* __restrict__ src, int x0)
{
    size_t i = ((size_t)(blockIdx.x + x0) * 256 + threadIdx.x) * 4;
    float4 v = __ldg((const float4*)(src + i));
    bf16 h0, h1, h2, h3, l0, l1, l2, l3;
    split1(v.x, h0, l0); split1(v.y, h1, l1);
    split1(v.z, h2, l2); split1(v.w, h3, l3);
    __nv_bfloat162* ph = (__nv_bfloat162*)(g_qh + i);
    __nv_bfloat162* pl = (__nv_bfloat162*)(g_ql + i);
    ph[0] = __nv_bfloat162(h0, h1); ph[1] = __nv_bfloat162(h2, h3);
    pl[0] = __nv_bfloat162(l0, l1); pl[1] = __nv_bfloat162(l2, l3);
}

// ---------------------------------------------------------------------------
// W fp32 [D][E] -> transposed hi/lo bf16 [E][D].
// ---------------------------------------------------------------------------
__global__ __launch_bounds__(256)
void trans_w(const float* __restrict__ src)
{
    __shared__ float t[32][33];
    const int r0 = blockIdx.y * 32, c0 = blockIdx.x * 32;
    const int tx = threadIdx.x & 31, ty = threadIdx.x >> 5;
    #pragma unroll
    for (int i = ty; i < 32; i += 8)
        t[i][tx] = src[(long)(r0 + i) * EE + c0 + tx];
    __syncthreads();
    const int a = threadIdx.x & 15, iy = threadIdx.x >> 4;
    #pragma unroll
    for (int p = 0; p < 2; ++p) {
        int i = iy + p * 16;
        float v0 = t[2 * a][i], v1 = t[2 * a + 1][i];
        bf16 h0, h1, l0, l1;
        split1(v0, h0, l0); split1(v1, h1, l1);
        long o = (long)(c0 + i) * DD + r0 + 2 * a;
        *(__nv_bfloat162*)(g_wth + o) = __nv_bfloat162(h0, h1);
        *(__nv_bfloat162*)(g_wtl + o) = __nv_bfloat162(l0, l1);
    }
}

// ---------------------------------------------------------------------------
// values fp32 [B][S][E]: one read -> g_vh/g_vl AND g_vth/g_vtl (transposed).
// ---------------------------------------------------------------------------
__global__ __launch_bounds__(256)
void prep_values(const float* __restrict__ src)
{
    __shared__ float t[32][33];
    const long zb = (long)blockIdx.z;
    src   += zb * SS * EE;
    bf16* vh  = g_vh  + zb * SS * EE;
    bf16* vl  = g_vl  + zb * SS * EE;
    bf16* vth = g_vth + zb * EE * SS;
    bf16* vtl = g_vtl + zb * EE * SS;
    const int r0 = blockIdx.y * 32, c0 = blockIdx.x * 32;
    const int tx = threadIdx.x & 31, ty = threadIdx.x >> 5;
    #pragma unroll
    for (int i = ty; i < 32; i += 8)
        t[i][tx] = src[(long)(r0 + i) * EE + c0 + tx];
    __syncthreads();
    const int a = threadIdx.x & 15, iy = threadIdx.x >> 4;
    #pragma unroll
    for (int p = 0; p < 2; ++p) {
        int i = iy + p * 16;
        {
            float v0 = t[i][2 * a], v1 = t[i][2 * a + 1];
            bf16 h0, h1, l0, l1;
            split1(v0, h0, l0); split1(v1, h1, l1);
            long o = (long)(r0 + i) * EE + c0 + 2 * a;
            *(__nv_bfloat162*)(vh + o) = __nv_bfloat162(h0, h1);
            *(__nv_bfloat162*)(vl + o) = __nv_bfloat162(l0, l1);
        }
        {
            float v0 = t[2 * a][i], v1 = t[2 * a + 1][i];
            bf16 h0, h1, l0, l1;
            split1(v0, h0, l0); split1(v1, h1, l1);
            long o = (long)(c0 + i) * SS + r0 + 2 * a;
            *(__nv_bfloat162*)(vth + o) = __nv_bfloat162(h0, h1);
            *(__nv_bfloat162*)(vtl + o) = __nv_bfloat162(l0, l1);
        }
    }
}

// ---------------------------------------------------------------------------
// NT GEMM on pre-split bf16 hi/lo operands, 3-stage cp.async, 1 sync/chunk.
// Fragment loads software-pipelined: B up-front, A rotated ahead of each
// 24-MMA block so LDSM latency hides under MMA issue.
// ASEL: 0=query, 1=tq, 2=attn.  BSEL: 0=wt, 1=values, 2=vt.
// EPI: 0=fp32, 1=fp32+mask, 2=split hi/lo to g_tqh/g_tql.
// z0 / y0: batch / M-tile offsets for the stream split.
// ---------------------------------------------------------------------------
template <int ASEL, int BSEL, int EPI, int CM, int CN>
__global__ __launch_bounds__(256, 1)
void mma_gemm(const int* __restrict__ maskg, float* __restrict__ Cg,
              int K, int ldc, long sA, long sB, long sC, int z0, int y0)
{
    constexpr int OFF_AH = 0;
    constexpr int OFF_AL = CM * ROWB;
    constexpr int OFF_BH = 2 * CM * ROWB;
    constexpr int OFF_BL = OFF_BH + CN * ROWB;
    constexpr int STAGEB = 2 * (CM + CN) * ROWB;
    constexpr int WM = CM / 64;
    extern __shared__ char smem[];
    const uint32_t sb = s2u(smem);
    const int tid = threadIdx.x, w = tid >> 5, lane = tid & 31;
    const int bz = blockIdx.z + z0;
    const bf16* Ah = ((ASEL == 0) ? g_qh : (ASEL == 1) ? g_tqh : g_ah) + (size_t)bz * sA;
    const bf16* Al = ((ASEL == 0) ? g_ql : (ASEL == 1) ? g_tql : g_al) + (size_t)bz * sA;
    const bf16* Bh = ((BSEL == 0) ? g_wth : (BSEL == 1) ? g_vh : g_vth) + (size_t)bz * sB;
    const bf16* Bl = ((BSEL == 0) ? g_wtl : (BSEL == 1) ? g_vl : g_vtl) + (size_t)bz * sB;
    float* C = Cg + (long)bz * sC;
    const int bm = (blockIdx.y + y0) * CM, bn = blockIdx.x * CN;
    const int m0 = (w % WM) * 64, n0 = (w / WM) * 64;

    float d[4][8][4] = {};

    auto load_stage = [&](uint32_t st, int kc) {
        uint32_t so = sb + st * STAGEB;
        #pragma unroll
        for (int j = 0; j < CM * 8 / 256; ++j) {
            int idx = tid + 256 * j;
            int half = idx / (CM * 4);
            int rem = idx - half * (CM * 4);
            int row = rem >> 2, q = rem & 3;
            const bf16* g = (half ? Al : Ah) + (size_t)(bm + row) * K + kc + q * 8;
            cp16(so + (half ? OFF_AL : OFF_AH) + row * ROWB + q * 16, g);
        }
        #pragma unroll
        for (int j = 0; j < CN * 8 / 256; ++j) {
            int idx = tid + 256 * j;
            int half = idx / (CN * 4);
            int rem = idx - half * (CN * 4);
            int row = rem >> 2, q = rem & 3;
            const bf16* g = (half ? Bl : Bh) + (size_t)(bn + row) * K + kc + q * 8;
            cp16(so + (half ? OFF_BL : OFF_BH) + row * ROWB + q * 16, g);
        }
    };

    load_stage(0, 0);
    CP_COMMIT();
    load_stage(1, BKC);
    CP_COMMIT();

    const int NC = K / BKC;
    for (int c = 0; c < NC; ++c) {
        CP_WAIT(1);
        __syncthreads();
        if (c + 2 < NC)
            load_stage((c + 2) % NSTAGE, (c + 2) * BKC);
        CP_COMMIT();
        const uint32_t stage = sb + (uint32_t)((c % NSTAGE) * STAGEB);
        #pragma unroll
        for (int ks = 0; ks < 2; ++ks) {
            uint32_t bh[8][2], bl[8][2];
            const uint32_t bkoff = ks * 32 + ((lane >> 3) & 1) * 16;
            #pragma unroll
            for (int np = 0; np < 4; ++np) {
                uint32_t ro = (uint32_t)((n0 + np * 16 + ((lane >> 4) << 3) + (lane & 7)) * ROWB);
                uint32_t r4[4];
                LDSM4(r4, stage + OFF_BH + ro + bkoff);
                bh[np*2][0] = r4[0]; bh[np*2][1] = r4[1];
                bh[np*2+1][0] = r4[2]; bh[np*2+1][1] = r4[3];
                LDSM4(r4, stage + OFF_BL + ro + bkoff);
                bl[np*2][0] = r4[0]; bl[np*2][1] = r4[1];
                bl[np*2+1][0] = r4[2]; bl[np*2+1][1] = r4[3];
            }
            // A fragments: 2-slot rotation, one m-tile ahead of the MMA block
            uint32_t ah2[2][4], al2[2][4];
            const uint32_t akoff = ks * 32 + (lane >> 4) * 16;
            {
                uint32_t ro = (uint32_t)((m0 + (lane & 15)) * ROWB);
                LDSM4(ah2[0], stage + OFF_AH + ro + akoff);
                LDSM4(al2[0], stage + OFF_AL + ro + akoff);
            }
            #pragma unroll
            for (int mt = 0; mt < 4; ++mt) {
                if (mt < 3) {
                    uint32_t ro = (uint32_t)((m0 + (mt + 1) * 16 + (lane & 15)) * ROWB);
                    LDSM4(ah2[(mt + 1) & 1], stage + OFF_AH + ro + akoff);
                    LDSM4(al2[(mt + 1) & 1], stage + OFF_AL + ro + akoff);
                }
                #pragma unroll
                for (int nt = 0; nt < 8; ++nt) {
                    MMA16816(d[mt][nt], ah2[mt & 1], bh[nt]);
                    MMA16816(d[mt][nt], ah2[mt & 1], bl[nt]);
                    MMA16816(d[mt][nt], al2[mt & 1], bh[nt]);
                }
            }
        }
    }

    const int* mrow = (EPI == 1) ? (maskg + (long)bz * ldc) : (const int*)0;
    #pragma unroll
    for (int mt = 0; mt < 4; ++mt) {
        #pragma unroll
        for (int nt = 0; nt < 8; ++nt) {
            int r0 = bm + m0 + mt * 16 + (lane >> 2);
            int col = bn + n0 + nt * 8 + (lane & 3) * 2;
            float v0 = d[mt][nt][0], v1 = d[mt][nt][1];
            float v2 = d[mt][nt][2], v3 = d[mt][nt][3];
            if (EPI == 1) {
                int k0 = __ldg(mrow + col), k1 = __ldg(mrow + col + 1);
                if (!k0) { v0 = -INFINITY; v2 = -INFINITY; }
                if (!k1) { v1 = -INFINITY; v3 = -INFINITY; }
            }
            if (EPI == 2) {
                size_t o0 = (size_t)r0 * ldc + col, o1 = (size_t)(r0 + 8) * ldc + col;
                bf16 h0, h1, h2, h3, l0, l1, l2, l3;
                split1(v0, h0, l0); split1(v1, h1, l1);
                split1(v2, h2, l2); split1(v3, h3, l3);
                *(__nv_bfloat162*)(g_tqh + o0) = __nv_bfloat162(h0, h1);
                *(__nv_bfloat162*)(g_tql + o0) = __nv_bfloat162(l0, l1);
                *(__nv_bfloat162*)(g_tqh + o1) = __nv_bfloat162(h2, h3);
                *(__nv_bfloat162*)(g_tql + o1) = __nv_bfloat162(l2, l3);
            } else {
                *(float2*)(C + (long)r0 * ldc + col)       = make_float2(v0, v1);
                *(float2*)(C + (long)(r0 + 8) * ldc + col) = make_float2(v2, v3);
            }
        }
    }
}

// ---------------------------------------------------------------------------
// In-place row softmax; emits hi/lo bf16 copy for G3. row0: stream offset.
// ---------------------------------------------------------------------------
__global__ __launch_bounds__(256)
void softmax_rows(float* __restrict__ attn, long row0)
{
    __shared__ float sm[32];
    const long row = row0 + blockIdx.x;
    float4* p = (float4*)(attn + row * (long)SS);
    const int t = threadIdx.x, lane = t & 31, wid = t >> 5;
    float4 v0 = p[t], v1 = p[t + 256];
    float m = fmaxf(fmaxf(fmaxf(v0.x, v0.y), fmaxf(v0.z, v0.w)),
                    fmaxf(fmaxf(v1.x, v1.y), fmaxf(v1.z, v1.w)));
    #pragma unroll
    for (int o = 16; o; o >>= 1) m = fmaxf(m, __shfl_xor_sync(0xffffffffu, m, o));
    if (lane == 0) sm[wid] = m;
    __syncthreads();
    if (t == 0) {
        float x = sm[0];
        #pragma unroll
        for (int i = 1; i < 8; ++i) x = fmaxf(x, sm[i]);
        sm[8] = x;
    }
    __syncthreads();
    const float rm = sm[8];
    v0.x = expf(v0.x - rm); v0.y = expf(v0.y - rm);
    v0.z = expf(v0.z - rm); v0.w = expf(v0.w - rm);
    v1.x = expf(v1.x - rm); v1.y = expf(v1.y - rm);
    v1.z = expf(v1.z - rm); v1.w = expf(v1.w - rm);
    float s = (v0.x + v0.y + v0.z + v0.w) + (v1.x + v1.y + v1.z + v1.w);
    #pragma unroll
    for (int o = 16; o; o >>= 1) s += __shfl_xor_sync(0xffffffffu, s, o);
    if (lane == 0) sm[16 + wid] = s;
    __syncthreads();
    if (t == 0) {
        float x = 0.0f;
        #pragma unroll
        for (int i = 0; i < 8; ++i) x += sm[16 + i];
        sm[24] = x;
    }
    __syncthreads();
    const float inv = 1.0f / sm[24];
    v0.x *= inv; v0.y *= inv; v0.z *= inv; v0.w *= inv;
    v1.x *= inv; v1.y *= inv; v1.z *= inv; v1.w *= inv;
    p[t] = v0; p[t + 256] = v1;

    const size_t base = (size_t)row * SS;
    float vv[8] = {v0.x, v0.y, v0.z, v0.w, v1.x, v1.y, v1.z, v1.w};
    size_t off[2] = {base + (size_t)t * 4, base + (size_t)(t + 256) * 4};
    #pragma unroll
    for (int g = 0; g < 2; ++g) {
        bf16 h0, h1, h2, h3, l0, l1, l2, l3;
        split1(vv[g*4+0], h0, l0); split1(vv[g*4+1], h1, l1);
        split1(vv[g*4+2], h2, l2); split1(vv[g*4+3], h3, l3);
        __nv_bfloat162* ph = (__nv_bfloat162*)(g_ah + off[g]);
        __nv_bfloat162* pl = (__nv_bfloat162*)(g_al + off[g]);
        ph[0] = __nv_bfloat162(h0, h1); ph[1] = __nv_bfloat162(h2, h3);
        pl[0] = __nv_bfloat162(l0, l1); pl[1] = __nv_bfloat162(l2, l3);
    }
}

extern "C" void kernel_launch(void* const* d_in, const int* in_sizes, int n_in,
                              void* d_out, int out_size)
{
    const float* query  = (const float*)d_in[0];
    const float* values = (const float*)d_in[1];
    const int*   mask   = (const int*)d_in[2];
    const float* W      = (const float*)d_in[3];

    float* context = (float*)d_out;
    float* attn    = (float*)d_out + (size_t)BB * QQ * EE;

    static cudaStream_t s2 = nullptr;
    static cudaEvent_t ev0 = nullptr, evW = nullptr, evPV = nullptr, evEnd = nullptr;
    if (!s2) {
        cudaStreamCreateWithFlags(&s2, cudaStreamNonBlocking);
        cudaEventCreateWithFlags(&ev0,  cudaEventDisableTiming);
        cudaEventCreateWithFlags(&evW,  cudaEventDisableTiming);
        cudaEventCreateWithFlags(&evPV, cudaEventDisableTiming);
        cudaEventCreateWithFlags(&evEnd, cudaEventDisableTiming);
    }

    cudaFuncSetAttribute(mma_gemm<0,0,2,256,128>, cudaFuncAttributeMaxDynamicSharedMemorySize, SMEM_SZ);
    cudaFuncSetAttribute(mma_gemm<1,1,1,128,256>, cudaFuncAttributeMaxDynamicSharedMemorySize, SMEM_SZ);
    cudaFuncSetAttribute(mma_gemm<2,2,0,256,128>, cudaFuncAttributeMaxDynamicSharedMemorySize, SMEM_SZ);

    // fork
    cudaEventRecord(ev0, 0);
    cudaStreamWaitEvent(s2, ev0, 0);

    // s0: query-lo split, W^T, G1 for batches 0-3 (rows 0..8191)
    conv_query<<<4096, 256>>>(query, 0);
    trans_w<<<dim3(EE/32, DD/32, 1), 256>>>(W);
    cudaEventRecord(evW, 0);
    mma_gemm<0,0,2,256,128><<<dim3(EE/128, 32, 1), 256, SMEM_SZ>>>(
        (const int*)0, (float*)0, DD, EE, 0L, 0L, 0L, 0, 0);

    // s2: values prep, query-hi split, G1 for batches 4-7 (needs W^T)
    prep_values<<<dim3(EE/32, SS/32, BB), 256, 0, s2>>>(values);
    cudaEventRecord(evPV, s2);
    conv_query<<<4096, 256, 0, s2>>>(query, 4096);
    cudaStreamWaitEvent(s2, evW, 0);
    mma_gemm<0,0,2,256,128><<<dim3(EE/128, 32, 1), 256, SMEM_SZ, s2>>>(
        (const int*)0, (float*)0, DD, EE, 0L, 0L, 0L, 0, 32);

    // chain A (batches 0-3) on s0 — needs prep_values from s2
    cudaStreamWaitEvent(0, evPV, 0);
    mma_gemm<1,1,1,128,256><<<dim3(SS/256, QQ/128, 4), 256, SMEM_SZ>>>(
        mask, attn, EE, SS, (long)QQ*EE, (long)SS*EE, (long)QQ*SS, 0, 0);
    softmax_rows<<<4*QQ, 256>>>(attn, 0L);
    mma_gemm<2,2,0,256,128><<<dim3(EE/128, QQ/256, 4), 256, SMEM_SZ>>>(
        (const int*)0, context, SS, EE, (long)QQ*SS, (long)EE*SS, (long)QQ*EE, 0, 0);

    // chain B (batches 4-7) on s2 — G1_hi and prep_values already on s2
    mma_gemm<1,1,1,128,256><<<dim3(SS/256, QQ/128, 4), 256, SMEM_SZ, s2>>>(
        mask, attn, EE, SS, (long)QQ*EE, (long)SS*EE, (long)QQ*SS, 4, 0);
    softmax_rows<<<4*QQ, 256, 0, s2>>>(attn, (long)4*QQ);
    mma_gemm<2,2,0,256,128><<<dim3(EE/128, QQ/256, 4), 256, SMEM_SZ, s2>>>(
        (const int*)0, context, SS, EE, (long)QQ*SS, (long)EE*SS, (long)QQ*EE, 4, 0);

    // join
    cudaEventRecord(evEnd, s2);
    cudaStreamWaitEvent(0, evEnd, 0);
}